// round 1
// baseline (speedup 1.0000x reference)
#include <cuda_runtime.h>
#include <cuda_fp16.h>

#define D 4096
#define NSTEPS 50

// fp16 copy of B, converted once per launch by prep_kernel.
// Static __device__ array: allowed (no runtime allocation).
__device__ __align__(16) __half g_Bh[(size_t)D * D];

// ---------------------------------------------------------------------------
// prep: B (fp32) -> g_Bh (fp16).  16.7M elements as float4 (4.19M float4s).
// ---------------------------------------------------------------------------
__global__ void __launch_bounds__(256) prep_kernel(const float* __restrict__ B) {
    int i = blockIdx.x * blockDim.x + threadIdx.x;  // float4 index
    const float4* B4 = (const float4*)B;
    float4 b = B4[i];
    __half2 h0 = __floats2half2_rn(b.x, b.y);
    __half2 h1 = __floats2half2_rn(b.z, b.w);
    uint2 packed;
    packed.x = *(unsigned int*)&h0;
    packed.y = *(unsigned int*)&h1;
    ((uint2*)g_Bh)[i] = packed;
}

// ---------------------------------------------------------------------------
// One recurrence step:  out[r] = dot(A[r], theta_t) + dot(Bh[r], theta_t - theta_{t-1})
// Grid: 512 CTAs x 256 threads; one warp per output row (8 rows/CTA).
// theta_t and dtheta staged in SMEM once per CTA; matrix rows streamed from
// L2 (A fp32 + B fp16 working set = 100.5 MB, L2-resident after step 1).
// ---------------------------------------------------------------------------
__global__ void __launch_bounds__(256) step_kernel(
    const float* __restrict__ A,
    const float* __restrict__ th1,   // theta_t
    const float* __restrict__ th0,   // theta_{t-1}
    float* __restrict__ out)         // theta_{t+1}
{
    __shared__ float4 s_t[D / 4];    // theta_t          (16 KB)
    __shared__ float4 s_d[D / 4];    // theta_t - theta_{t-1} (16 KB)

    int tid = threadIdx.x;
    const float4* v1 = (const float4*)th1;
    const float4* v0 = (const float4*)th0;
#pragma unroll
    for (int i = 0; i < 4; ++i) {
        int idx = tid + i * 256;
        float4 a = v1[idx];
        float4 b = v0[idx];
        s_t[idx] = a;
        s_d[idx] = make_float4(a.x - b.x, a.y - b.y, a.z - b.z, a.w - b.w);
    }
    __syncthreads();

    int warp = tid >> 5;
    int lane = tid & 31;
    int row  = (blockIdx.x << 3) + warp;

    const float4* aRow = (const float4*)(A + (size_t)row * D);       // 1024 float4
    const uint2*  bRow = (const uint2*)(g_Bh + (size_t)row * D);     // 1024 uint2 (4 halves)

    float acc = 0.0f;

    // A (fp32) . theta_t : 32 float4 per lane, coalesced 512B per warp-iter
#pragma unroll 8
    for (int i = 0; i < 32; ++i) {
        int idx = i * 32 + lane;
        float4 a = aRow[idx];
        float4 t = s_t[idx];
        acc = fmaf(a.x, t.x, acc);
        acc = fmaf(a.y, t.y, acc);
        acc = fmaf(a.z, t.z, acc);
        acc = fmaf(a.w, t.w, acc);
    }

    // B (fp16) . dtheta : 32 uint2 per lane (4 halves each), conflict-free LDS.128
#pragma unroll 8
    for (int i = 0; i < 32; ++i) {
        int idx = i * 32 + lane;
        uint2 b4 = bRow[idx];
        float4 d = s_d[idx];
        __half2 h;
        float2 f;
        h = *(__half2*)&b4.x; f = __half22float2(h);
        acc = fmaf(f.x, d.x, acc);
        acc = fmaf(f.y, d.y, acc);
        h = *(__half2*)&b4.y; f = __half22float2(h);
        acc = fmaf(f.x, d.z, acc);
        acc = fmaf(f.y, d.w, acc);
    }

    // Warp reduction
#pragma unroll
    for (int off = 16; off; off >>= 1)
        acc += __shfl_xor_sync(0xffffffffu, acc, off);

    if (lane == 0) out[row] = acc;
}

// ---------------------------------------------------------------------------
// Launch: prep once, then 50 dependent step kernels.  Trajectory rows in
// d_out double as the state history (theta_{t} = out[t-1]).
// Graph-capturable: kernel launches only, no sync, no allocation.
// ---------------------------------------------------------------------------
extern "C" void kernel_launch(void* const* d_in, const int* in_sizes, int n_in,
                              void* d_out, int out_size) {
    const float* init = (const float*)d_in[0];  // [2, D]
    const float* A    = (const float*)d_in[1];  // [D, D]
    const float* B    = (const float*)d_in[2];  // [D, D]
    float* out = (float*)d_out;                 // [NSTEPS, D]

    prep_kernel<<<(D * (size_t)D / 4) / 256, 256>>>(B);

    const float* th1 = init + D;  // theta_t      = init_seq[-1]
    const float* th0 = init;      // theta_{t-1}  = init_seq[-2]
    for (int t = 0; t < NSTEPS; ++t) {
        step_kernel<<<D / 8, 256>>>(A, th1, th0, out + (size_t)t * D);
        th0 = th1;
        th1 = out + (size_t)t * D;
    }
}

// round 2
// speedup vs baseline: 1.7059x; 1.7059x over previous
#include <cuda_runtime.h>
#include <cuda_fp16.h>

#define D 4096
#define NSTEPS 50

// Quantized matrix copies, built once per launch by prep kernels.
// A is stored as "fp24": hi 16 bits (sign+exp+7 mantissa) + next mantissa byte,
// in two separate arrays for coalesced access.  B is fp16.
// Total static footprint: 33.5 + 16.8 + 33.5 = 83.8 MB  (66% of L2 -> resident).
__device__ __align__(16) unsigned short g_Ahi[(size_t)D * D];
__device__ __align__(16) unsigned char  g_Amid[(size_t)D * D];
__device__ __align__(16) __half         g_Bh[(size_t)D * D];

// ---------------------------------------------------------------------------
// prep A: fp32 -> (hi u16, mid u8), round-to-nearest at mantissa bit 8.
// Processes 4 elements per thread.
// ---------------------------------------------------------------------------
__global__ void __launch_bounds__(256) prepA_kernel(const float* __restrict__ A) {
    int i = blockIdx.x * blockDim.x + threadIdx.x;      // float4 index
    float4 a = ((const float4*)A)[i];
    unsigned int u0 = __float_as_uint(a.x) + 0x80u;     // round at bit 7->8
    unsigned int u1 = __float_as_uint(a.y) + 0x80u;
    unsigned int u2 = __float_as_uint(a.z) + 0x80u;
    unsigned int u3 = __float_as_uint(a.w) + 0x80u;
    uint2 hi;
    hi.x = (u0 >> 16) | (u1 & 0xFFFF0000u);
    hi.y = (u2 >> 16) | (u3 & 0xFFFF0000u);
    unsigned int mid = ((u0 >> 8)  & 0x000000FFu) |
                       ((u1)       & 0x0000FF00u) |
                       ((u2 << 8)  & 0x00FF0000u) |
                       ((u3 << 16) & 0xFF000000u);
    ((uint2*)g_Ahi)[i]        = hi;
    ((unsigned int*)g_Amid)[i] = mid;
}

// ---------------------------------------------------------------------------
// prep B: fp32 -> fp16
// ---------------------------------------------------------------------------
__global__ void __launch_bounds__(256) prepB_kernel(const float* __restrict__ B) {
    int i = blockIdx.x * blockDim.x + threadIdx.x;
    float4 b = ((const float4*)B)[i];
    __half2 h0 = __floats2half2_rn(b.x, b.y);
    __half2 h1 = __floats2half2_rn(b.z, b.w);
    uint2 packed;
    packed.x = *(unsigned int*)&h0;
    packed.y = *(unsigned int*)&h1;
    ((uint2*)g_Bh)[i] = packed;
}

// ---------------------------------------------------------------------------
// One recurrence step: out[r] = dot(A24[r], theta_t) + dot(Bh[r], theta_t - theta_{t-1})
// 512 CTAs x 256 threads, one warp per output row.
// Matrix data streams from L2 (83.8 MB resident WS); vectors staged in SMEM.
// ---------------------------------------------------------------------------
__global__ void __launch_bounds__(256) step_kernel(
    const float* __restrict__ th1,   // theta_t
    const float* __restrict__ th0,   // theta_{t-1}
    float* __restrict__ out)         // theta_{t+1}
{
    __shared__ float4 s_t[D / 4];    // theta_t               (16 KB)
    __shared__ float4 s_d[D / 4];    // theta_t - theta_{t-1} (16 KB)

    int tid = threadIdx.x;
    const float4* v1 = (const float4*)th1;
    const float4* v0 = (const float4*)th0;
#pragma unroll
    for (int i = 0; i < 4; ++i) {
        int idx = tid + i * 256;
        float4 a = v1[idx];
        float4 b = v0[idx];
        s_t[idx] = a;
        s_d[idx] = make_float4(a.x - b.x, a.y - b.y, a.z - b.z, a.w - b.w);
    }
    __syncthreads();

    int warp = tid >> 5;
    int lane = tid & 31;
    int row  = (blockIdx.x << 3) + warp;

    const uint2* hiRow  = (const uint2*)(g_Ahi  + (size_t)row * D);  // 4 elts / uint2
    const unsigned int* midRow = (const unsigned int*)(g_Amid + (size_t)row * D); // 4 / u32
    const uint2* bRow   = (const uint2*)(g_Bh   + (size_t)row * D);  // 4 halves / uint2

    float acc = 0.0f;

#pragma unroll 4
    for (int i = 0; i < 32; ++i) {
        int idx = i * 32 + lane;
        uint2 h = hiRow[idx];
        unsigned int m = midRow[idx];
        uint2 bb = bRow[idx];
        float4 t = s_t[idx];
        float4 dv = s_d[idx];

        // Reconstruct fp24 -> fp32:  bytes (b3..b0) = [hi1, hi0, mid, 0]
        float a0 = __uint_as_float(__byte_perm(m, h.x, 0x5400) & 0xFFFFFF00u);
        float a1 = __uint_as_float(__byte_perm(m, h.x, 0x7610) & 0xFFFFFF00u);
        float a2 = __uint_as_float(__byte_perm(m, h.y, 0x5420) & 0xFFFFFF00u);
        float a3 = __uint_as_float(__byte_perm(m, h.y, 0x7630) & 0xFFFFFF00u);
        acc = fmaf(a0, t.x, acc);
        acc = fmaf(a1, t.y, acc);
        acc = fmaf(a2, t.z, acc);
        acc = fmaf(a3, t.w, acc);

        // B (fp16) . dtheta
        float2 f0 = __half22float2(*(__half2*)&bb.x);
        float2 f1 = __half22float2(*(__half2*)&bb.y);
        acc = fmaf(f0.x, dv.x, acc);
        acc = fmaf(f0.y, dv.y, acc);
        acc = fmaf(f1.x, dv.z, acc);
        acc = fmaf(f1.y, dv.w, acc);
    }

    // Warp reduction
#pragma unroll
    for (int off = 16; off; off >>= 1)
        acc += __shfl_xor_sync(0xffffffffu, acc, off);

    if (lane == 0) out[row] = acc;
}

// ---------------------------------------------------------------------------
// Launch: prep once, then 50 dependent step kernels.  Trajectory rows in
// d_out double as the state history.
// ---------------------------------------------------------------------------
extern "C" void kernel_launch(void* const* d_in, const int* in_sizes, int n_in,
                              void* d_out, int out_size) {
    const float* init = (const float*)d_in[0];  // [2, D]
    const float* A    = (const float*)d_in[1];  // [D, D]
    const float* B    = (const float*)d_in[2];  // [D, D]
    float* out = (float*)d_out;                 // [NSTEPS, D]

    const int n4 = (D * D) / 4;                 // float4 count
    prepA_kernel<<<n4 / 256, 256>>>(A);
    prepB_kernel<<<n4 / 256, 256>>>(B);

    const float* th1 = init + D;  // theta_t      = init_seq[-1]
    const float* th0 = init;      // theta_{t-1}  = init_seq[-2]
    for (int t = 0; t < NSTEPS; ++t) {
        step_kernel<<<D / 8, 256>>>(th1, th0, out + (size_t)t * D);
        th0 = th1;
        th1 = out + (size_t)t * D;
    }
}

// round 3
// speedup vs baseline: 1.9478x; 1.1418x over previous
#include <cuda_runtime.h>
#include <cuda_fp16.h>

#define D 4096
#define NSTEPS 50
#define NCTA 128
#define NTHREADS 1024

// Interleaved fp16 matrices: g_AB[r*2D + 2j] = A[r][j], [.. + 1] = B[r][j].
// 67 MB static -> fully L2-resident (53% of 126 MB).
__device__ __align__(16) __half g_AB[(size_t)2 * D * D];
__device__ unsigned int g_bar;   // global step barrier counter (monotonic)

// ---------------------------------------------------------------------------
// prep: interleave A,B into fp16 pairs; also reset the barrier counter so
// every launch (incl. each graph replay) starts from 0.
// ---------------------------------------------------------------------------
__global__ void __launch_bounds__(256) prep_kernel(const float* __restrict__ A,
                                                   const float* __restrict__ B) {
    if (blockIdx.x == 0 && threadIdx.x == 0) g_bar = 0;
    size_t i = (size_t)blockIdx.x * blockDim.x + threadIdx.x;  // float4 index
    float4 a = ((const float4*)A)[i];
    float4 b = ((const float4*)B)[i];
    uint4 o;
    __half2 p;
    p = __floats2half2_rn(a.x, b.x); o.x = *(unsigned int*)&p;
    p = __floats2half2_rn(a.y, b.y); o.y = *(unsigned int*)&p;
    p = __floats2half2_rn(a.z, b.z); o.z = *(unsigned int*)&p;
    p = __floats2half2_rn(a.w, b.w); o.w = *(unsigned int*)&p;
    ((uint4*)g_AB)[i] = o;   // dest uint4 i == pairs for elements 4i..4i+3
}

// ---------------------------------------------------------------------------
// Persistent recurrence kernel: 128 CTAs x 1024 threads, one warp per row
// (32 rows/CTA), all 50 steps in one launch with a device-wide barrier.
// All 128 CTAs are co-resident (<= 148 SMs, 32KB smem, 1024 thr) so the
// spin barrier cannot deadlock.  Deterministic: arrival order is irrelevant.
// ---------------------------------------------------------------------------
__global__ void __launch_bounds__(NTHREADS) rnn_kernel(const float* __restrict__ init,
                                                       float* __restrict__ out) {
    __shared__ float4 s_t[D / 4];    // theta_t               (16 KB)
    __shared__ float4 s_d[D / 4];    // theta_t - theta_{t-1} (16 KB)

    int tid  = threadIdx.x;
    int warp = tid >> 5;
    int lane = tid & 31;
    int row  = blockIdx.x * 32 + warp;
    const uint4* abRow = (const uint4*)(g_AB + (size_t)row * 2 * D);  // 1024 uint4

    for (int t = 0; t < NSTEPS; ++t) {
        // Stage theta_t and delta into SMEM (L2 loads; fresh addresses each step)
        const float* th1 = (t == 0) ? init + D : out + (size_t)(t - 1) * D;
        const float* th0 = (t == 0) ? init
                         : (t == 1) ? init + D
                                    : out + (size_t)(t - 2) * D;
        float4 a = __ldcg((const float4*)th1 + tid);
        float4 b = __ldcg((const float4*)th0 + tid);
        s_t[tid] = a;
        s_d[tid] = make_float4(a.x - b.x, a.y - b.y, a.z - b.z, a.w - b.w);
        __syncthreads();

        float acc = 0.0f;
#pragma unroll 8
        for (int i = 0; i < 32; ++i) {
            int idx = i * 32 + lane;
            uint4 v   = abRow[idx];       // 4 (a,b) fp16 pairs
            float4 tt = s_t[idx];
            float4 dd = s_d[idx];
            float2 f;
            f = __half22float2(*(__half2*)&v.x);
            acc = fmaf(f.x, tt.x, acc); acc = fmaf(f.y, dd.x, acc);
            f = __half22float2(*(__half2*)&v.y);
            acc = fmaf(f.x, tt.y, acc); acc = fmaf(f.y, dd.y, acc);
            f = __half22float2(*(__half2*)&v.z);
            acc = fmaf(f.x, tt.z, acc); acc = fmaf(f.y, dd.z, acc);
            f = __half22float2(*(__half2*)&v.w);
            acc = fmaf(f.x, tt.w, acc); acc = fmaf(f.y, dd.w, acc);
        }

#pragma unroll
        for (int off = 16; off; off >>= 1)
            acc += __shfl_xor_sync(0xffffffffu, acc, off);

        if (lane == 0) {
            out[(size_t)t * D + row] = acc;
            __threadfence();             // make row visible gpu-wide (release)
        }
        __syncthreads();                 // all warps of CTA wrote + fenced

        if (tid == 0) {
            atomicAdd(&g_bar, 1u);
            unsigned int target = (unsigned int)(t + 1) * NCTA;
            while (*(volatile unsigned int*)&g_bar < target) { }
            __threadfence();             // acquire
        }
        __syncthreads();                 // release CTA into next step
    }
}

// ---------------------------------------------------------------------------
// Launch: prep (convert + barrier reset), then ONE persistent kernel.
// Graph-capturable: kernel launches only.
// ---------------------------------------------------------------------------
extern "C" void kernel_launch(void* const* d_in, const int* in_sizes, int n_in,
                              void* d_out, int out_size) {
    const float* init = (const float*)d_in[0];  // [2, D]
    const float* A    = (const float*)d_in[1];  // [D, D]
    const float* B    = (const float*)d_in[2];  // [D, D]
    float* out = (float*)d_out;                 // [NSTEPS, D]

    prep_kernel<<<(D * (size_t)D / 4) / 256, 256>>>(A, B);
    rnn_kernel<<<NCTA, NTHREADS>>>(init, out);
}

// round 4
// speedup vs baseline: 2.5862x; 1.3278x over previous
#include <cuda_runtime.h>
#include <cuda_fp16.h>

#define D 4096
#define NSTEPS 50
#define NCTA 147
#define ROWS_PER_CTA 28
#define NTHREADS 1024

// Interleaved fp16 matrices: g_AB[r*2D + 2j] = A[r][j], [.. + 1] = B[r][j].
// 67 MB static -> fully L2-resident.
__device__ __align__(16) __half g_AB[(size_t)2 * D * D];
__device__ unsigned int g_bar;   // global step barrier counter (monotonic per launch)

// ---------------------------------------------------------------------------
// prep: interleave A,B into fp16 pairs; reset the barrier counter.
// ---------------------------------------------------------------------------
__global__ void __launch_bounds__(256) prep_kernel(const float* __restrict__ A,
                                                   const float* __restrict__ B) {
    if (blockIdx.x == 0 && threadIdx.x == 0) g_bar = 0;
    size_t i = (size_t)blockIdx.x * blockDim.x + threadIdx.x;  // float4 index
    float4 a = ((const float4*)A)[i];
    float4 b = ((const float4*)B)[i];
    uint4 o;
    __half2 p;
    p = __floats2half2_rn(a.x, b.x); o.x = *(unsigned int*)&p;
    p = __floats2half2_rn(a.y, b.y); o.y = *(unsigned int*)&p;
    p = __floats2half2_rn(a.z, b.z); o.z = *(unsigned int*)&p;
    p = __floats2half2_rn(a.w, b.w); o.w = *(unsigned int*)&p;
    ((uint4*)g_AB)[i] = o;
}

// acc += A[j]*t + B[j]*d for 4 interleaved (a,b) fp16 pairs in m
__device__ __forceinline__ float dotAB(uint4 m, float4 t, float4 d, float acc) {
    float2 f;
    f = __half22float2(*(__half2*)&m.x); acc = fmaf(f.x, t.x, acc); acc = fmaf(f.y, d.x, acc);
    f = __half22float2(*(__half2*)&m.y); acc = fmaf(f.x, t.y, acc); acc = fmaf(f.y, d.y, acc);
    f = __half22float2(*(__half2*)&m.z); acc = fmaf(f.x, t.z, acc); acc = fmaf(f.y, d.z, acc);
    f = __half22float2(*(__half2*)&m.w); acc = fmaf(f.x, t.w, acc); acc = fmaf(f.y, d.w, acc);
    return acc;
}

// ---------------------------------------------------------------------------
// Persistent recurrence kernel: 147 CTAs x 1024 threads, 28 rows/CTA.
// Warp w (< 28): rg = w>>2 picks a 4-row group, ks = w&3 picks a 1024-element
// K-segment.  Vector float4s are loaded from SMEM once and reused for 4 rows
// (4x less LDS traffic than 1-row-per-warp).  Partial dots combined via SMEM.
// All 147 CTAs co-resident (1 CTA/SM) -> spin barrier is deadlock-free.
// ---------------------------------------------------------------------------
__global__ void __launch_bounds__(NTHREADS, 1) rnn_kernel(const float* __restrict__ init,
                                                          float* __restrict__ out) {
    __shared__ float4 s_t[D / 4];                    // theta_t   (16 KB)
    __shared__ float4 s_d[D / 4];                    // delta     (16 KB)
    __shared__ float  s_part[ROWS_PER_CTA * 4];      // per-(row,ks) partials

    const int tid  = threadIdx.x;
    const int warp = tid >> 5;
    const int lane = tid & 31;
    const int rg   = warp >> 2;                      // 0..6 (+ inactive 7)
    const int ks   = warp & 3;                       // 0..3
    const int row_base = blockIdx.x * ROWS_PER_CTA;
    const int row0 = row_base + rg * 4;
    const bool active = (warp < ROWS_PER_CTA) && (row0 < D);
    const int seg = ks * 256;                        // float4 offset of segment

    const uint4* r0 = (const uint4*)g_AB + (size_t)(row0 + 0) * 1024;
    const uint4* r1 = (const uint4*)g_AB + (size_t)(row0 + 1) * 1024;
    const uint4* r2 = (const uint4*)g_AB + (size_t)(row0 + 2) * 1024;
    const uint4* r3 = (const uint4*)g_AB + (size_t)(row0 + 3) * 1024;

    // Prologue: s_t holds theta_{-1} = init_seq[0]
    s_t[tid] = ((const float4*)init)[tid];

    for (int t = 0; t < NSTEPS; ++t) {
        // Stage theta_t; delta = theta_t - theta_{t-1} (prev step's s_t)
        const float* th1 = (t == 0) ? init + D : out + (size_t)(t - 1) * D;
        float4 nt = __ldcg((const float4*)th1 + tid);
        float4 pt = s_t[tid];
        s_t[tid] = nt;
        s_d[tid] = make_float4(nt.x - pt.x, nt.y - pt.y, nt.z - pt.z, nt.w - pt.w);
        __syncthreads();

        if (active) {
            float acc0 = 0.f, acc1 = 0.f, acc2 = 0.f, acc3 = 0.f;
#pragma unroll 2
            for (int i = 0; i < 8; ++i) {
                int idx = seg + i * 32 + lane;
                float4 t4 = s_t[idx];
                float4 d4 = s_d[idx];
                uint4 m0 = r0[idx];
                uint4 m1 = r1[idx];
                uint4 m2 = r2[idx];
                uint4 m3 = r3[idx];
                acc0 = dotAB(m0, t4, d4, acc0);
                acc1 = dotAB(m1, t4, d4, acc1);
                acc2 = dotAB(m2, t4, d4, acc2);
                acc3 = dotAB(m3, t4, d4, acc3);
            }
#pragma unroll
            for (int off = 16; off; off >>= 1) {
                acc0 += __shfl_xor_sync(0xffffffffu, acc0, off);
                acc1 += __shfl_xor_sync(0xffffffffu, acc1, off);
                acc2 += __shfl_xor_sync(0xffffffffu, acc2, off);
                acc3 += __shfl_xor_sync(0xffffffffu, acc3, off);
            }
            if (lane == 0) {
                s_part[(rg * 4 + 0) * 4 + ks] = acc0;
                s_part[(rg * 4 + 1) * 4 + ks] = acc1;
                s_part[(rg * 4 + 2) * 4 + ks] = acc2;
                s_part[(rg * 4 + 3) * 4 + ks] = acc3;
            }
        }
        __syncthreads();

        // Combine K-segment partials (deterministic order) and publish the row
        if (tid < ROWS_PER_CTA) {
            int row = row_base + tid;
            if (row < D) {
                float v = (s_part[tid * 4 + 0] + s_part[tid * 4 + 1]) +
                          (s_part[tid * 4 + 2] + s_part[tid * 4 + 3]);
                __stcg(out + (size_t)t * D + row, v);
                __threadfence();          // release: row visible gpu-wide
            }
        }
        __syncthreads();

        // Device-wide step barrier
        if (tid == 0) {
            atomicAdd(&g_bar, 1u);
            unsigned int target = (unsigned int)(t + 1) * NCTA;
            while (*(volatile unsigned int*)&g_bar < target) { }
            __threadfence();              // acquire
        }
        __syncthreads();
    }
}

// ---------------------------------------------------------------------------
// Launch: prep (convert + barrier reset), then ONE persistent kernel.
// ---------------------------------------------------------------------------
extern "C" void kernel_launch(void* const* d_in, const int* in_sizes, int n_in,
                              void* d_out, int out_size) {
    const float* init = (const float*)d_in[0];  // [2, D]
    const float* A    = (const float*)d_in[1];  // [D, D]
    const float* B    = (const float*)d_in[2];  // [D, D]
    float* out = (float*)d_out;                 // [NSTEPS, D]

    prep_kernel<<<(D * (size_t)D / 4) / 256, 256>>>(A, B);
    rnn_kernel<<<NCTA, NTHREADS>>>(init, out);
}

// round 5
// speedup vs baseline: 2.6736x; 1.0338x over previous
#include <cuda_runtime.h>
#include <cuda_fp16.h>

#define D 4096
#define NSTEPS 50
#define NCTA 147
#define ROWS_PER_CTA 28
#define CACHED_ROWS 12           // rows per CTA held in SMEM (192 KB)
#define NTHREADS 1024

// Interleaved fp16 matrices: g_AB[r*2D + 2j] = A[r][j], [.. + 1] = B[r][j].
__device__ __align__(16) __half g_AB[(size_t)2 * D * D];
__device__ unsigned int g_bar;   // global step barrier counter (monotonic per launch)

// ---------------------------------------------------------------------------
// prep: interleave A,B into fp16 pairs; reset the barrier counter.
// ---------------------------------------------------------------------------
__global__ void __launch_bounds__(256) prep_kernel(const float* __restrict__ A,
                                                   const float* __restrict__ B) {
    if (blockIdx.x == 0 && threadIdx.x == 0) g_bar = 0;
    size_t i = (size_t)blockIdx.x * blockDim.x + threadIdx.x;  // float4 index
    float4 a = ((const float4*)A)[i];
    float4 b = ((const float4*)B)[i];
    uint4 o;
    __half2 p;
    p = __floats2half2_rn(a.x, b.x); o.x = *(unsigned int*)&p;
    p = __floats2half2_rn(a.y, b.y); o.y = *(unsigned int*)&p;
    p = __floats2half2_rn(a.z, b.z); o.z = *(unsigned int*)&p;
    p = __floats2half2_rn(a.w, b.w); o.w = *(unsigned int*)&p;
    ((uint4*)g_AB)[i] = o;
}

// acc += A[j]*t + B[j]*d for 4 interleaved (a,b) fp16 pairs in m
__device__ __forceinline__ float dotAB(uint4 m, float4 t, float4 d, float acc) {
    float2 f;
    f = __half22float2(*(__half2*)&m.x); acc = fmaf(f.x, t.x, acc); acc = fmaf(f.y, d.x, acc);
    f = __half22float2(*(__half2*)&m.y); acc = fmaf(f.x, t.y, acc); acc = fmaf(f.y, d.y, acc);
    f = __half22float2(*(__half2*)&m.z); acc = fmaf(f.x, t.z, acc); acc = fmaf(f.y, d.z, acc);
    f = __half22float2(*(__half2*)&m.w); acc = fmaf(f.x, t.w, acc); acc = fmaf(f.y, d.w, acc);
    return acc;
}

// ---------------------------------------------------------------------------
// Persistent recurrence kernel: 147 CTAs x 1024 threads, 28 rows/CTA.
// Rows 0..11 of each CTA's slice are preloaded into SMEM ONCE (192 KB) and
// read via LDS every step; rows 12..27 stream from L2.  Per-step chip L2
// traffic drops 67 -> 37.6 MB.  Warp (rg, ks): rg = 4-row group, ks = 1024-
// element K-segment; vector float4s reused across the 4 rows.
// Dynamic SMEM layout: s_t 16K | s_d 16K | s_part 512B | s_mat 192K = 224.5K.
// ---------------------------------------------------------------------------
__global__ void __launch_bounds__(NTHREADS, 1) rnn_kernel(const float* __restrict__ init,
                                                          float* __restrict__ out) {
    extern __shared__ char smem[];
    float4* s_t    = (float4*)smem;                    // theta_t   (16 KB)
    float4* s_d    = (float4*)(smem + 16384);          // delta     (16 KB)
    float*  s_part = (float*)(smem + 32768);           // partials  (512 B)
    uint4*  s_mat  = (uint4*)(smem + 33280);           // cached rows (192 KB)

    const int tid  = threadIdx.x;
    const int warp = tid >> 5;
    const int lane = tid & 31;
    const int rg   = warp >> 2;                        // 0..7 (7 idle)
    const int ks   = warp & 3;                         // 0..3
    const int row_base = blockIdx.x * ROWS_PER_CTA;
    const int row0 = row_base + rg * 4;
    const bool active = (rg < 7) && (row0 + 3 < D || row0 < D);
    const bool rowOK  = (rg < 7) && (row0 < D);
    const bool cached = (rg < CACHED_ROWS / 4);        // rg 0..2 -> SMEM rows
    const int seg = ks * 256;                          // float4 offset of segment

    // Preload 12 cached rows into SMEM (once).  Clamp OOB rows of the last CTA.
#pragma unroll
    for (int it = 0; it < CACHED_ROWS; ++it) {
        int src_row = row_base + it;
        if (src_row >= D) src_row = D - 1;
        s_mat[it * 1024 + tid] = ((const uint4*)g_AB)[(size_t)src_row * 1024 + tid];
    }

    // Streamed-row pointers (rg >= 3)
    const uint4* r0 = (const uint4*)g_AB + (size_t)min(row0 + 0, D - 1) * 1024;
    const uint4* r1 = (const uint4*)g_AB + (size_t)min(row0 + 1, D - 1) * 1024;
    const uint4* r2 = (const uint4*)g_AB + (size_t)min(row0 + 2, D - 1) * 1024;
    const uint4* r3 = (const uint4*)g_AB + (size_t)min(row0 + 3, D - 1) * 1024;
    // Cached-row pointers (rg < 3)
    const uint4* c0 = s_mat + (size_t)(rg * 4 + 0) * 1024;
    const uint4* c1 = s_mat + (size_t)(rg * 4 + 1) * 1024;
    const uint4* c2 = s_mat + (size_t)(rg * 4 + 2) * 1024;
    const uint4* c3 = s_mat + (size_t)(rg * 4 + 3) * 1024;

    // Prologue: s_t holds theta_{-1} = init_seq[0]
    s_t[tid] = ((const float4*)init)[tid];

    for (int t = 0; t < NSTEPS; ++t) {
        // Stage theta_t; delta = theta_t - theta_{t-1} (prev step's s_t)
        const float* th1 = (t == 0) ? init + D : out + (size_t)(t - 1) * D;
        float4 nt = __ldcg((const float4*)th1 + tid);
        float4 pt = s_t[tid];
        s_t[tid] = nt;
        s_d[tid] = make_float4(nt.x - pt.x, nt.y - pt.y, nt.z - pt.z, nt.w - pt.w);
        __syncthreads();

        if (rowOK) {
            float acc0 = 0.f, acc1 = 0.f, acc2 = 0.f, acc3 = 0.f;
            if (cached) {
#pragma unroll 2
                for (int i = 0; i < 8; ++i) {
                    int idx = seg + i * 32 + lane;
                    float4 t4 = s_t[idx];
                    float4 d4 = s_d[idx];
                    acc0 = dotAB(c0[idx], t4, d4, acc0);
                    acc1 = dotAB(c1[idx], t4, d4, acc1);
                    acc2 = dotAB(c2[idx], t4, d4, acc2);
                    acc3 = dotAB(c3[idx], t4, d4, acc3);
                }
            } else {
#pragma unroll 2
                for (int i = 0; i < 8; ++i) {
                    int idx = seg + i * 32 + lane;
                    float4 t4 = s_t[idx];
                    float4 d4 = s_d[idx];
                    uint4 m0 = r0[idx];
                    uint4 m1 = r1[idx];
                    uint4 m2 = r2[idx];
                    uint4 m3 = r3[idx];
                    acc0 = dotAB(m0, t4, d4, acc0);
                    acc1 = dotAB(m1, t4, d4, acc1);
                    acc2 = dotAB(m2, t4, d4, acc2);
                    acc3 = dotAB(m3, t4, d4, acc3);
                }
            }
#pragma unroll
            for (int off = 16; off; off >>= 1) {
                acc0 += __shfl_xor_sync(0xffffffffu, acc0, off);
                acc1 += __shfl_xor_sync(0xffffffffu, acc1, off);
                acc2 += __shfl_xor_sync(0xffffffffu, acc2, off);
                acc3 += __shfl_xor_sync(0xffffffffu, acc3, off);
            }
            if (lane == 0) {
                s_part[(rg * 4 + 0) * 4 + ks] = acc0;
                s_part[(rg * 4 + 1) * 4 + ks] = acc1;
                s_part[(rg * 4 + 2) * 4 + ks] = acc2;
                s_part[(rg * 4 + 3) * 4 + ks] = acc3;
            }
        }
        __syncthreads();

        // Combine K-segment partials (deterministic order) and publish the row
        if (tid < ROWS_PER_CTA) {
            int row = row_base + tid;
            if (row < D) {
                float v = (s_part[tid * 4 + 0] + s_part[tid * 4 + 1]) +
                          (s_part[tid * 4 + 2] + s_part[tid * 4 + 3]);
                __stcg(out + (size_t)t * D + row, v);
                __threadfence();          // release: row visible gpu-wide
            }
        }
        __syncthreads();

        // Device-wide step barrier (all 147 CTAs co-resident: 1 CTA/SM)
        if (tid == 0) {
            atomicAdd(&g_bar, 1u);
            unsigned int target = (unsigned int)(t + 1) * NCTA;
            while (*(volatile unsigned int*)&g_bar < target) { }
            __threadfence();              // acquire
        }
        __syncthreads();
    }
}

// ---------------------------------------------------------------------------
// Launch: prep (convert + barrier reset), then ONE persistent kernel with
// opt-in 224.5 KB dynamic SMEM.
// ---------------------------------------------------------------------------
extern "C" void kernel_launch(void* const* d_in, const int* in_sizes, int n_in,
                              void* d_out, int out_size) {
    const float* init = (const float*)d_in[0];  // [2, D]
    const float* A    = (const float*)d_in[1];  // [D, D]
    const float* B    = (const float*)d_in[2];  // [D, D]
    float* out = (float*)d_out;                 // [NSTEPS, D]

    const int smem_bytes = 33280 + CACHED_ROWS * 1024 * 16;  // 229,888 B
    cudaFuncSetAttribute(rnn_kernel, cudaFuncAttributeMaxDynamicSharedMemorySize,
                         smem_bytes);

    prep_kernel<<<(D * (size_t)D / 4) / 256, 256>>>(A, B);
    rnn_kernel<<<NCTA, NTHREADS, smem_bytes>>>(init, out);
}